// round 16
// baseline (speedup 1.0000x reference)
#include <cuda_runtime.h>
#include <cuda_bf16.h>
#include <cstdint>

// ---------------- problem constants ----------------
#define BATCH 256
#define TSEQ  2048
#define SOBS  39
#define AACT  4
#define HID   256
#define EPS   1e-5f

#define TILE_M  64
#define NTILES  8192                 // BATCH*TSEQ/TILE_M
#define TPB     32                   // tiles per batch
#define GRID    296                  // 2 CTAs per SM
#define THREADS 256                  // 8 warps: mgrp=warp>>2 (m32), ngrp=warp&3 (n64)

#define PITCH   264
#define ROWB    (PITCH*2)            // 528 bytes per k-row
#define PLANE_B (16*ROWB)            // 8448
#define CHUNK_B (2*PLANE_B)          // 16896 (hi plane + lo plane)
#define NCHK    19                   // 3 W1 chunks (k48) + 16 W2 chunks (k256)

// ---------------- global scratch ----------------
__device__ __align__(16) unsigned char g_wimg[NCHK * CHUNK_B];
__device__ float g_partials[NTILES * 8];          // per-warp partials (no tile-end syncs)
__device__ unsigned int g_arrive = 0;

// ---------------- smem byte offsets (from 128-aligned base) ----------------
// A2 slots keyed (ki*4+midx): xs staging (11008B) aliases ki<=5 slots only,
// so the next tile's xs TMA can be issued after GEMM2 chunk ki=5.
#define A2H_OFF  0        // 32768
#define A2L_OFF  32768    // 32768
#define WBUF_OFF 65536    // 2 slots * 16896 = 33792
#define VEC_OFF  99328    // 7 * 1024
#define LNX_OFF  106496   // 64 rows * 4 ngrp * 2 floats = 2048
#define MBAR_OFF 108544   // full0,full1,empty0,empty1,xsb,xse : 6*8 = 48
#define FLAG_OFF 108592   // 4
#define SMEM_DYN 108928

// ---------------- PTX helpers ----------------
__device__ __forceinline__ uint32_t smem_u32(const void* p) {
    uint32_t a;
    asm("{ .reg .u64 t; cvta.to.shared.u64 t, %1; cvt.u32.u64 %0, t; }" : "=r"(a) : "l"(p));
    return a;
}
#define MBARRIER_INIT(addr, cnt) \
    asm volatile("mbarrier.init.shared.b64 [%0], %1;" :: "r"(addr), "r"(cnt) : "memory")
#define MBARRIER_EXPECT_TX(addr, bytes) \
    asm volatile("mbarrier.arrive.expect_tx.shared.b64 _, [%0], %1;" :: "r"(addr), "r"(bytes) : "memory")
#define MBARRIER_ARRIVE(addr) \
    asm volatile("mbarrier.arrive.shared.b64 _, [%0];" :: "r"(addr) : "memory")
#define BAR_MGRP(id) \
    asm volatile("bar.sync %0, 128;" :: "r"(id) : "memory")

#define MBARRIER_WAIT_PARITY(mbar_addr, phase_parity) do { \
    uint32_t _mbar = (uint32_t)(mbar_addr); \
    uint32_t _par  = (uint32_t)(phase_parity); \
    asm volatile( \
        "{\n\t" \
        ".reg .pred P1;\n\t" \
        "WAIT_LOOP_%=:\n\t" \
        "mbarrier.try_wait.parity.acquire.cta.shared::cta.b64 P1, [%0], %1, 0x989680;\n\t" \
        "@P1 bra.uni WAIT_DONE_%=;\n\t" \
        "bra.uni WAIT_LOOP_%=;\n\t" \
        "WAIT_DONE_%=:\n\t" \
        "}" :: "r"(_mbar), "r"(_par) : "memory"); \
} while (0)

__device__ __forceinline__ void bulk_g2s(uint32_t dst, const void* src, uint32_t bytes, uint32_t mbar) {
    uint64_t gsrc;
    asm("cvta.to.global.u64 %0, %1;" : "=l"(gsrc) : "l"(src));
    asm volatile(
        "cp.async.bulk.shared::cluster.global.mbarrier::complete_tx::bytes [%0], [%1], %2, [%3];"
        :: "r"(dst), "l"(gsrc), "r"(bytes), "r"(mbar) : "memory");
}

__device__ __forceinline__ void ldsm4t(uint32_t& r0, uint32_t& r1, uint32_t& r2, uint32_t& r3,
                                       uint32_t addr) {
    asm volatile("ldmatrix.sync.aligned.m8n8.x4.trans.shared.b16 {%0,%1,%2,%3}, [%4];"
                 : "=r"(r0), "=r"(r1), "=r"(r2), "=r"(r3) : "r"(addr));
}
__device__ __forceinline__ void mma16816(float* c, const uint32_t* a, uint32_t b0, uint32_t b1) {
    asm volatile(
        "mma.sync.aligned.m16n8k16.row.col.f32.bf16.bf16.f32 "
        "{%0,%1,%2,%3}, {%4,%5,%6,%7}, {%8,%9}, {%0,%1,%2,%3};"
        : "+f"(c[0]), "+f"(c[1]), "+f"(c[2]), "+f"(c[3])
        : "r"(a[0]), "r"(a[1]), "r"(a[2]), "r"(a[3]), "r"(b0), "r"(b1));
}
__device__ __forceinline__ uint32_t pack_bf16x2(float lo, float hi) {
    uint32_t r;
    asm("cvt.rn.bf16x2.f32 %0, %1, %2;" : "=r"(r) : "f"(hi), "f"(lo));
    return r;
}
__device__ __forceinline__ void split2(float vx, float vy, uint32_t& h, uint32_t& l) {
    h = pack_bf16x2(vx, vy);
    float hx = __bfloat162float(__ushort_as_bfloat16((unsigned short)(h & 0xffffu)));
    float hy = __bfloat162float(__ushort_as_bfloat16((unsigned short)(h >> 16)));
    l = pack_bf16x2(vx - hx, vy - hy);
}
__device__ __forceinline__ float warp_sum(float v) {
    #pragma unroll
    for (int off = 16; off; off >>= 1) v += __shfl_xor_sync(0xffffffffu, v, off);
    return v;
}
__device__ __forceinline__ float quad_sum(float v) {
    v += __shfl_xor_sync(0xffffffffu, v, 1);
    v += __shfl_xor_sync(0xffffffffu, v, 2);
    return v;
}

// ---------------- prep: split weights into 19-chunk SMEM-image ring ----------------
__global__ void prep_kernel(const float* __restrict__ W1, const float* __restrict__ W2)
{
    int idx = blockIdx.x * blockDim.x + threadIdx.x;
    const int TOT = NCHK * 16 * PITCH;   // 80256
    if (idx >= TOT) return;
    int c = idx / (16 * PITCH);
    int rem = idx - c * 16 * PITCH;
    int r = rem / PITCH, n = rem % PITCH;
    int k = c * 16 + r;
    float v = 0.f;
    if (n < 256) {
        if (c < 3) { if (k < 43) v = W1[k * 256 + n]; }
        else       v = W2[(k - 48) * 256 + n];
    }
    __nv_bfloat16 h = __float2bfloat16(v);
    __nv_bfloat16 l = __float2bfloat16(v - __bfloat162float(h));
    unsigned char* base = g_wimg + c * CHUNK_B + r * ROWB + n * 2;
    *(__nv_bfloat16*)base             = h;
    *(__nv_bfloat16*)(base + PLANE_B) = l;
}

// ---------------- main fused kernel ----------------
__global__ __launch_bounds__(THREADS, 2)
void fused_mma_kernel(const float* __restrict__ obs, const float* __restrict__ act,
                      const float* __restrict__ b1,  const float* __restrict__ g1,
                      const float* __restrict__ be1, const float* __restrict__ b2,
                      const float* __restrict__ g2,  const float* __restrict__ be2,
                      const float* __restrict__ W3,  const float* __restrict__ b3,
                      float* __restrict__ out)
{
    extern __shared__ char raw[];
    char* sm = (char*)((((uintptr_t)raw) + 127) & ~(uintptr_t)127);
    const uint32_t sbase = smem_u32(sm);
    const int tid = threadIdx.x, warp = tid >> 5, lane = tid & 31;
    const int mgrp = warp >> 2;             // 0..1 : rows mgrp*32..+31
    const int ngrp = warp & 3;              // 0..3 : cols ngrp*64..+63
    const int qr = lane >> 2;               // 0..7
    const int qc = (lane & 3) << 1;         // 0,2,4,6

    float* xsO  = (float*)(sm + A2H_OFF);           // [64][39] packed
    float* xsA  = (float*)(sm + A2H_OFF + 9984);    // [64][4]
    float* b1s  = (float*)(sm + VEC_OFF);
    float* g1s  = b1s + 256;  float* be1s = g1s + 256;
    float* b2s  = be1s + 256; float* g2s  = b2s + 256; float* be2s = g2s + 256;
    float* w3s  = be2s + 256;
    float* lnx  = (float*)(sm + LNX_OFF);           // [64 rows][4 ngrp][2]
    unsigned int* flag = (unsigned int*)(sm + FLAG_OFF);

    const uint32_t mbf[2] = {sbase + MBAR_OFF,      sbase + MBAR_OFF + 8};
    const uint32_t mbe[2] = {sbase + MBAR_OFF + 16, sbase + MBAR_OFF + 24};
    const uint32_t xsb    =  sbase + MBAR_OFF + 32;
    const uint32_t xse    =  sbase + MBAR_OFF + 40;
    const uint32_t slot[2] = {sbase + WBUF_OFF, sbase + WBUF_OFF + CHUNK_B};

    b1s[tid] = b1[tid]; g1s[tid] = g1[tid]; be1s[tid] = be1[tid];
    b2s[tid] = b2[tid]; g2s[tid] = g2[tid]; be2s[tid] = be2[tid];
    w3s[tid] = W3[tid];

    if (tid == 0) {
        MBARRIER_INIT(mbf[0], 1); MBARRIER_INIT(mbf[1], 1);
        MBARRIER_INIT(mbe[0], 8); MBARRIER_INIT(mbe[1], 8);
        MBARRIER_INIT(xsb, 1);
        MBARRIER_INIT(xse, 8);
    }
    __syncthreads();

    const int ntl = (NTILES - blockIdx.x + GRID - 1) / GRID;
    const int total_ch = ntl * NCHK;

    if (tid == 0) {
        // prime xs for first tile
        MBARRIER_EXPECT_TX(xsb, 11008u);
        bulk_g2s(sbase + A2H_OFF, (const char*)obs + (size_t)blockIdx.x * 9984, 9984u, xsb);
        bulk_g2s(sbase + A2H_OFF + 9984, (const char*)act + (size_t)blockIdx.x * 1024, 1024u, xsb);
        // prime weight chunks 0,1
        MBARRIER_EXPECT_TX(mbf[0], CHUNK_B);
        bulk_g2s(slot[0], g_wimg, CHUNK_B, mbf[0]);
        if (total_ch > 1) {
            MBARRIER_EXPECT_TX(mbf[1], CHUNK_B);
            bulk_g2s(slot[1], g_wimg + CHUNK_B, CHUNK_B, mbf[1]);
        }
    }

    const uint32_t ldsm_off = (uint32_t)((lane & 15) * ROWB + ((lane >> 4) << 3) * 2 + ngrp * 128);
    int fp0 = 0, fp1 = 0, ep0 = 0, ep1 = 0, xp = 0, xp2 = 0;
    int g = 0;    // global chunk cursor
    int lt = 0;

    for (int tile = blockIdx.x; tile < NTILES; tile += GRID, ++lt) {
        MBARRIER_WAIT_PARITY(xsb, xp); xp ^= 1;

        float c[2][8][4];
        #pragma unroll
        for (int mf = 0; mf < 2; mf++)
            #pragma unroll
            for (int nf = 0; nf < 8; nf++)
                { c[mf][nf][0]=0.f; c[mf][nf][1]=0.f; c[mf][nf][2]=0.f; c[mf][nf][3]=0.f; }

        // ---- GEMM1: 3 weight chunks (k48), A from xs ----
        #pragma unroll 1
        for (int cc = 0; cc < 3; ++cc, ++g) {
            const int s = g & 1;
            MBARRIER_WAIT_PARITY(mbf[s], s ? fp1 : fp0);
            if (s) fp1 ^= 1; else fp0 ^= 1;

            uint32_t ah[2][4], al[2][4];
            #pragma unroll
            for (int mf = 0; mf < 2; mf++) {
                int r = mgrp * 32 + mf * 16 + qr;
                int c0 = cc * 16 + qc;
                float v[8];
                #pragma unroll
                for (int t = 0; t < 4; t++) {
                    int rr = r + (t & 1) * 8;
                    int cx = c0 + (t >> 1) * 8;
                    #pragma unroll
                    for (int e = 0; e < 2; e++) {
                        int ci = cx + e;
                        float vv = 0.f;
                        if (ci < SOBS) vv = xsO[rr * SOBS + ci];
                        else if (ci < SOBS + AACT) vv = xsA[rr * AACT + ci - SOBS];
                        v[t * 2 + e] = vv;
                    }
                }
                split2(v[0], v[1], ah[mf][0], al[mf][0]);
                split2(v[2], v[3], ah[mf][1], al[mf][1]);
                split2(v[4], v[5], ah[mf][2], al[mf][2]);
                split2(v[6], v[7], ah[mf][3], al[mf][3]);
            }

            uint32_t bb = slot[s] + ldsm_off;
            #pragma unroll
            for (int nf2 = 0; nf2 < 4; nf2++) {
                uint32_t h0, h1, h2, h3, l0, l1, l2, l3;
                ldsm4t(h0, h1, h2, h3, bb + nf2 * 32);
                ldsm4t(l0, l1, l2, l3, bb + PLANE_B + nf2 * 32);
                #pragma unroll
                for (int mf = 0; mf < 2; mf++) {
                    mma16816(c[mf][2*nf2],   ah[mf], h0, h1);
                    mma16816(c[mf][2*nf2+1], ah[mf], h2, h3);
                    mma16816(c[mf][2*nf2],   ah[mf], l0, l1);
                    mma16816(c[mf][2*nf2+1], ah[mf], l2, l3);
                    mma16816(c[mf][2*nf2],   al[mf], h0, h1);
                    mma16816(c[mf][2*nf2+1], al[mf], h2, h3);
                }
            }
            if (lane == 0) MBARRIER_ARRIVE(mbe[s]);
            if (tid == 0 && g + 2 < total_ch) {
                MBARRIER_WAIT_PARITY(mbe[s], s ? ep1 : ep0);
                if (s) ep1 ^= 1; else ep0 ^= 1;
                int cc2 = (g + 2) % NCHK;
                MBARRIER_EXPECT_TX(mbf[s], CHUNK_B);
                bulk_g2s(slot[s], g_wimg + cc2 * CHUNK_B, CHUNK_B, mbf[s]);
            }
        }

        // ---- LN1 (cross-4-warp stats) + ReLU -> A2 fragments ----
        {
            float st[4] = {0,0,0,0}, sq[4] = {0,0,0,0};
            #pragma unroll
            for (int mf = 0; mf < 2; mf++)
                #pragma unroll
                for (int nf = 0; nf < 8; nf++) {
                    float2 bb2 = *(const float2*)&b1s[ngrp * 64 + nf * 8 + qc];
                    float* cf = c[mf][nf];
                    cf[0] += bb2.x; cf[1] += bb2.y; cf[2] += bb2.x; cf[3] += bb2.y;
                    st[mf*2]   += cf[0] + cf[1];
                    sq[mf*2]    = fmaf(cf[0], cf[0], fmaf(cf[1], cf[1], sq[mf*2]));
                    st[mf*2+1] += cf[2] + cf[3];
                    sq[mf*2+1]  = fmaf(cf[2], cf[2], fmaf(cf[3], cf[3], sq[mf*2+1]));
                }
            #pragma unroll
            for (int i = 0; i < 4; i++) { st[i] = quad_sum(st[i]); sq[i] = quad_sum(sq[i]); }
            if ((lane & 3) == 0) {
                #pragma unroll
                for (int i = 0; i < 4; i++) {
                    int row = mgrp * 32 + (i >> 1) * 16 + (i & 1) * 8 + qr;
                    *(float2*)&lnx[(row * 4 + ngrp) * 2] = make_float2(st[i], sq[i]);
                }
            }
            __syncthreads();   // CTA-wide: also guards A2 writes vs other mgrp's xs reads
            float mu[4], rs[4];
            #pragma unroll
            for (int i = 0; i < 4; i++) {
                int row = mgrp * 32 + (i >> 1) * 16 + (i & 1) * 8 + qr;
                float4 p0 = *(const float4*)&lnx[row * 8];
                float4 p1 = *(const float4*)&lnx[row * 8 + 4];
                float s = p0.x + p0.z + p1.x + p1.z;
                float q = p0.y + p0.w + p1.y + p1.w;
                float m = s * (1.f / HID);
                float var = q * (1.f / HID) - m * m + EPS;
                float r0 = rsqrtf(var); r0 = r0 * (1.5f - 0.5f * var * r0 * r0);
                mu[i] = m; rs[i] = r0;
            }
            #pragma unroll
            for (int mf = 0; mf < 2; mf++) {
                float m0 = mu[mf*2], r0 = rs[mf*2], m1 = mu[mf*2+1], r1 = rs[mf*2+1];
                int midx = mgrp * 2 + mf;
                #pragma unroll
                for (int j = 0; j < 4; j++) {
                    uint32_t hh[4], ll[4];
                    #pragma unroll
                    for (int t = 0; t < 2; t++) {
                        int nf = 2 * j + t;
                        int ncol = ngrp * 64 + nf * 8 + qc;
                        float2 gg = *(const float2*)&g1s[ncol];
                        float2 ee = *(const float2*)&be1s[ncol];
                        float* cf = c[mf][nf];
                        float v0 = fmaxf((cf[0] - m0) * r0 * gg.x + ee.x, 0.f);
                        float v1 = fmaxf((cf[1] - m0) * r0 * gg.y + ee.y, 0.f);
                        float v2 = fmaxf((cf[2] - m1) * r1 * gg.x + ee.x, 0.f);
                        float v3 = fmaxf((cf[3] - m1) * r1 * gg.y + ee.y, 0.f);
                        split2(v0, v1, hh[t*2],   ll[t*2]);
                        split2(v2, v3, hh[t*2+1], ll[t*2+1]);
                    }
                    int ki = ngrp * 4 + j;
                    uint32_t so = (uint32_t)(((ki * 4 + midx) * 32 + lane) * 16);
                    *(uint4*)(sm + A2H_OFF + so) = make_uint4(hh[0], hh[1], hh[2], hh[3]);
                    *(uint4*)(sm + A2L_OFF + so) = make_uint4(ll[0], ll[1], ll[2], ll[3]);
                }
            }
            BAR_MGRP(1 + mgrp);   // A2 slots for this mgrp written; only same-mgrp warps read them
        }

        // ---- GEMM2: 16 weight chunks (k256), A from A2 fragments ----
        #pragma unroll
        for (int mf = 0; mf < 2; mf++)
            #pragma unroll
            for (int nf = 0; nf < 8; nf++)
                { c[mf][nf][0]=0.f; c[mf][nf][1]=0.f; c[mf][nf][2]=0.f; c[mf][nf][3]=0.f; }

        // -- sub-loop A: chunks ki 0..5 (these A2 slots alias the xs region) --
        #pragma unroll 1
        for (int cc = 3; cc < 9; ++cc, ++g) {
            const int s = g & 1;
            MBARRIER_WAIT_PARITY(mbf[s], s ? fp1 : fp0);
            if (s) fp1 ^= 1; else fp0 ^= 1;

            const int ki = cc - 3;
            uint32_t ah[2][4], al[2][4];
            #pragma unroll
            for (int mf = 0; mf < 2; mf++) {
                int midx = mgrp * 2 + mf;
                uint32_t so = (uint32_t)(((ki * 4 + midx) * 32 + lane) * 16);
                uint4 a4 = *(const uint4*)(sm + A2H_OFF + so);
                uint4 b4 = *(const uint4*)(sm + A2L_OFF + so);
                ah[mf][0]=a4.x; ah[mf][1]=a4.y; ah[mf][2]=a4.z; ah[mf][3]=a4.w;
                al[mf][0]=b4.x; al[mf][1]=b4.y; al[mf][2]=b4.z; al[mf][3]=b4.w;
            }

            uint32_t bb = slot[s] + ldsm_off;
            #pragma unroll
            for (int nf2 = 0; nf2 < 4; nf2++) {
                uint32_t h0, h1, h2, h3, l0, l1, l2, l3;
                ldsm4t(h0, h1, h2, h3, bb + nf2 * 32);
                ldsm4t(l0, l1, l2, l3, bb + PLANE_B + nf2 * 32);
                #pragma unroll
                for (int mf = 0; mf < 2; mf++) {
                    mma16816(c[mf][2*nf2],   ah[mf], h0, h1);
                    mma16816(c[mf][2*nf2+1], ah[mf], h2, h3);
                    mma16816(c[mf][2*nf2],   ah[mf], l0, l1);
                    mma16816(c[mf][2*nf2+1], ah[mf], l2, l3);
                    mma16816(c[mf][2*nf2],   al[mf], h0, h1);
                    mma16816(c[mf][2*nf2+1], al[mf], h2, h3);
                }
            }
            if (lane == 0) MBARRIER_ARRIVE(mbe[s]);
            if (tid == 0 && g + 2 < total_ch) {
                MBARRIER_WAIT_PARITY(mbe[s], s ? ep1 : ep0);
                if (s) ep1 ^= 1; else ep0 ^= 1;
                int cc2 = (g + 2) % NCHK;
                MBARRIER_EXPECT_TX(mbf[s], CHUNK_B);
                bulk_g2s(slot[s], g_wimg + cc2 * CHUNK_B, CHUNK_B, mbf[s]);
            }
        }

        // -- between sub-loops (once per tile, cold): release xs region, prefetch next xs --
        if (lane == 0) MBARRIER_ARRIVE(xse);
        if (tid == 0 && lt + 1 < ntl) {
            MBARRIER_WAIT_PARITY(xse, xp2);
            size_t nt = (size_t)(tile + GRID);
            MBARRIER_EXPECT_TX(xsb, 11008u);
            bulk_g2s(sbase + A2H_OFF, (const char*)obs + nt * 9984, 9984u, xsb);
            bulk_g2s(sbase + A2H_OFF + 9984, (const char*)act + nt * 1024, 1024u, xsb);
        }
        xp2 ^= 1;

        // -- sub-loop B: chunks ki 6..15 --
        #pragma unroll 1
        for (int cc = 9; cc < NCHK; ++cc, ++g) {
            const int s = g & 1;
            MBARRIER_WAIT_PARITY(mbf[s], s ? fp1 : fp0);
            if (s) fp1 ^= 1; else fp0 ^= 1;

            const int ki = cc - 3;
            uint32_t ah[2][4], al[2][4];
            #pragma unroll
            for (int mf = 0; mf < 2; mf++) {
                int midx = mgrp * 2 + mf;
                uint32_t so = (uint32_t)(((ki * 4 + midx) * 32 + lane) * 16);
                uint4 a4 = *(const uint4*)(sm + A2H_OFF + so);
                uint4 b4 = *(const uint4*)(sm + A2L_OFF + so);
                ah[mf][0]=a4.x; ah[mf][1]=a4.y; ah[mf][2]=a4.z; ah[mf][3]=a4.w;
                al[mf][0]=b4.x; al[mf][1]=b4.y; al[mf][2]=b4.z; al[mf][3]=b4.w;
            }

            uint32_t bb = slot[s] + ldsm_off;
            #pragma unroll
            for (int nf2 = 0; nf2 < 4; nf2++) {
                uint32_t h0, h1, h2, h3, l0, l1, l2, l3;
                ldsm4t(h0, h1, h2, h3, bb + nf2 * 32);
                ldsm4t(l0, l1, l2, l3, bb + PLANE_B + nf2 * 32);
                #pragma unroll
                for (int mf = 0; mf < 2; mf++) {
                    mma16816(c[mf][2*nf2],   ah[mf], h0, h1);
                    mma16816(c[mf][2*nf2+1], ah[mf], h2, h3);
                    mma16816(c[mf][2*nf2],   ah[mf], l0, l1);
                    mma16816(c[mf][2*nf2+1], ah[mf], l2, l3);
                    mma16816(c[mf][2*nf2],   al[mf], h0, h1);
                    mma16816(c[mf][2*nf2+1], al[mf], h2, h3);
                }
            }
            if (lane == 0) MBARRIER_ARRIVE(mbe[s]);
            if (tid == 0 && g + 2 < total_ch) {
                MBARRIER_WAIT_PARITY(mbe[s], s ? ep1 : ep0);
                if (s) ep1 ^= 1; else ep0 ^= 1;
                int cc2 = (g + 2) % NCHK;
                MBARRIER_EXPECT_TX(mbf[s], CHUNK_B);
                bulk_g2s(slot[s], g_wimg + cc2 * CHUNK_B, CHUNK_B, mbf[s]);
            }
        }

        // ---- LN2 + ReLU + dot(W3) ----
        float rp = 0.f;
        {
            float st[4] = {0,0,0,0}, sq[4] = {0,0,0,0};
            #pragma unroll
            for (int mf = 0; mf < 2; mf++)
                #pragma unroll
                for (int nf = 0; nf < 8; nf++) {
                    float2 bb2 = *(const float2*)&b2s[ngrp * 64 + nf * 8 + qc];
                    float* cf = c[mf][nf];
                    cf[0] += bb2.x; cf[1] += bb2.y; cf[2] += bb2.x; cf[3] += bb2.y;
                    st[mf*2]   += cf[0] + cf[1];
                    sq[mf*2]    = fmaf(cf[0], cf[0], fmaf(cf[1], cf[1], sq[mf*2]));
                    st[mf*2+1] += cf[2] + cf[3];
                    sq[mf*2+1]  = fmaf(cf[2], cf[2], fmaf(cf[3], cf[3], sq[mf*2+1]));
                }
            #pragma unroll
            for (int i = 0; i < 4; i++) { st[i] = quad_sum(st[i]); sq[i] = quad_sum(sq[i]); }
            if ((lane & 3) == 0) {
                #pragma unroll
                for (int i = 0; i < 4; i++) {
                    int row = mgrp * 32 + (i >> 1) * 16 + (i & 1) * 8 + qr;
                    *(float2*)&lnx[(row * 4 + ngrp) * 2] = make_float2(st[i], sq[i]);
                }
            }
            BAR_MGRP(1 + mgrp);   // lnx rows are mgrp-local
            float mu[4], rs[4];
            #pragma unroll
            for (int i = 0; i < 4; i++) {
                int row = mgrp * 32 + (i >> 1) * 16 + (i & 1) * 8 + qr;
                float4 p0 = *(const float4*)&lnx[row * 8];
                float4 p1 = *(const float4*)&lnx[row * 8 + 4];
                float s = p0.x + p0.z + p1.x + p1.z;
                float q = p0.y + p0.w + p1.y + p1.w;
                float m = s * (1.f / HID);
                float var = q * (1.f / HID) - m * m + EPS;
                float r0 = rsqrtf(var); r0 = r0 * (1.5f - 0.5f * var * r0 * r0);
                mu[i] = m; rs[i] = r0;
            }
            #pragma unroll
            for (int mf = 0; mf < 2; mf++) {
                float m0 = mu[mf*2], r0 = rs[mf*2], m1 = mu[mf*2+1], r1 = rs[mf*2+1];
                #pragma unroll
                for (int nf = 0; nf < 8; nf++) {
                    int ncol = ngrp * 64 + nf * 8 + qc;
                    float2 gg = *(const float2*)&g2s[ncol];
                    float2 ee = *(const float2*)&be2s[ncol];
                    float2 ww = *(const float2*)&w3s[ncol];
                    float* cf = c[mf][nf];
                    float v0 = fmaxf((cf[0] - m0) * r0 * gg.x + ee.x, 0.f);
                    float v1 = fmaxf((cf[1] - m0) * r0 * gg.y + ee.y, 0.f);
                    float v2 = fmaxf((cf[2] - m1) * r1 * gg.x + ee.x, 0.f);
                    float v3 = fmaxf((cf[3] - m1) * r1 * gg.y + ee.y, 0.f);
                    rp = fmaf(v0, ww.x, rp); rp = fmaf(v1, ww.y, rp);
                    rp = fmaf(v2, ww.x, rp); rp = fmaf(v3, ww.y, rp);
                }
            }
        }
        rp = warp_sum(rp);
        if (lane == 0) g_partials[(size_t)tile * 8 + warp] = rp;
        // no tile-end CTA syncs: next-tile A2 overwrite is guarded by LN1's __syncthreads
    }

    // ---- last-block deterministic reduction into out[] ----
    __syncthreads();            // all warps' g_partials writes issued
    __threadfence();
    if (tid == 0) {
        unsigned int old = atomicAdd(&g_arrive, 1u);
        *flag = (old == GRID - 1) ? 1u : 0u;
    }
    __syncthreads();
    if (*flag) {
        __threadfence();
        float bb3 = b3[0];
        for (int b = tid; b < BATCH; b += THREADS) {
            float t = (float)TSEQ * bb3;
            #pragma unroll 4
            for (int i = 0; i < TPB * 8; i++)
                t += __ldcg(&g_partials[(size_t)b * TPB * 8 + i]);
            out[b] = t;
        }
        __syncthreads();
        if (tid == 0) { g_arrive = 0; __threadfence(); }
    }
}

extern "C" void kernel_launch(void* const* d_in, const int* in_sizes, int n_in,
                              void* d_out, int out_size)
{
    const float* obs = (const float*)d_in[0];
    const float* act = (const float*)d_in[1];
    const float* W1  = (const float*)d_in[2];
    const float* b1  = (const float*)d_in[3];
    const float* g1  = (const float*)d_in[4];
    const float* be1 = (const float*)d_in[5];
    const float* W2  = (const float*)d_in[6];
    const float* b2  = (const float*)d_in[7];
    const float* g2  = (const float*)d_in[8];
    const float* be2 = (const float*)d_in[9];
    const float* W3  = (const float*)d_in[10];
    const float* b3  = (const float*)d_in[11];

    prep_kernel<<<(NCHK * 16 * PITCH + 255) / 256, 256>>>(W1, W2);

    cudaFuncSetAttribute(fused_mma_kernel,
                         cudaFuncAttributeMaxDynamicSharedMemorySize, SMEM_DYN);
    fused_mma_kernel<<<GRID, THREADS, SMEM_DYN>>>(obs, act, b1, g1, be1, b2, g2, be2,
                                                  W3, b3, (float*)d_out);
}

// round 17
// speedup vs baseline: 1.0791x; 1.0791x over previous
#include <cuda_runtime.h>
#include <cuda_bf16.h>
#include <cstdint>

// ---------------- problem constants ----------------
#define BATCH 256
#define TSEQ  2048
#define SOBS  39
#define AACT  4
#define HID   256
#define EPS   1e-5f

#define TILE_M  64
#define NTILES  8192                 // BATCH*TSEQ/TILE_M
#define TPB     32                   // tiles per batch
#define GRID    296                  // 2 CTAs per SM
#define THREADS 256                  // 8 warps: mgrp=warp>>2 (m32), ngrp=warp&3 (n64)

#define PITCH   264
#define ROWB    (PITCH*2)            // 528 bytes per k-row
#define PLANE_B (16*ROWB)            // 8448
#define CHUNK_B (2*PLANE_B)          // 16896 (hi plane + lo plane)
#define NCHK    19                   // 3 W1 chunks (k48) + 16 W2 chunks (k256)

// ---------------- global scratch ----------------
__device__ __align__(16) unsigned char g_wimg[NCHK * CHUNK_B];
__device__ float g_partials[NTILES];
__device__ unsigned int g_arrive = 0;

// ---------------- smem byte offsets (from 128-aligned base) ----------------
// A2 slots keyed (ki*4+midx): xs staging (11008B) aliases ki<=5 slots only,
// so the next tile's xs TMA can be issued after GEMM2 chunk ki=5.
#define A2H_OFF  0        // 32768
#define A2L_OFF  32768    // 32768
#define WBUF_OFF 65536    // 2 slots * 16896 = 33792
#define VEC_OFF  99328    // 7 * 1024
#define LNX_OFF  106496   // 64 rows * 4 ngrp * 2 floats = 2048
#define BSUM_OFF 108544   // 8 floats
#define MBAR_OFF 108576   // full0,full1,empty0,empty1,xsb,xse : 6*8 = 48
#define FLAG_OFF 108624   // 4
#define SMEM_DYN 108928

// ---------------- PTX helpers ----------------
__device__ __forceinline__ uint32_t smem_u32(const void* p) {
    uint32_t a;
    asm("{ .reg .u64 t; cvta.to.shared.u64 t, %1; cvt.u32.u64 %0, t; }" : "=r"(a) : "l"(p));
    return a;
}
#define MBARRIER_INIT(addr, cnt) \
    asm volatile("mbarrier.init.shared.b64 [%0], %1;" :: "r"(addr), "r"(cnt) : "memory")
#define MBARRIER_EXPECT_TX(addr, bytes) \
    asm volatile("mbarrier.arrive.expect_tx.shared.b64 _, [%0], %1;" :: "r"(addr), "r"(bytes) : "memory")
#define MBARRIER_ARRIVE(addr) \
    asm volatile("mbarrier.arrive.shared.b64 _, [%0];" :: "r"(addr) : "memory")
#define BAR_MGRP(id) \
    asm volatile("bar.sync %0, 128;" :: "r"(id) : "memory")

#define MBARRIER_WAIT_PARITY(mbar_addr, phase_parity) do { \
    uint32_t _mbar = (uint32_t)(mbar_addr); \
    uint32_t _par  = (uint32_t)(phase_parity); \
    asm volatile( \
        "{\n\t" \
        ".reg .pred P1;\n\t" \
        "WAIT_LOOP_%=:\n\t" \
        "mbarrier.try_wait.parity.acquire.cta.shared::cta.b64 P1, [%0], %1, 0x989680;\n\t" \
        "@P1 bra.uni WAIT_DONE_%=;\n\t" \
        "bra.uni WAIT_LOOP_%=;\n\t" \
        "WAIT_DONE_%=:\n\t" \
        "}" :: "r"(_mbar), "r"(_par) : "memory"); \
} while (0)

__device__ __forceinline__ void bulk_g2s(uint32_t dst, const void* src, uint32_t bytes, uint32_t mbar) {
    uint64_t gsrc;
    asm("cvta.to.global.u64 %0, %1;" : "=l"(gsrc) : "l"(src));
    asm volatile(
        "cp.async.bulk.shared::cluster.global.mbarrier::complete_tx::bytes [%0], [%1], %2, [%3];"
        :: "r"(dst), "l"(gsrc), "r"(bytes), "r"(mbar) : "memory");
}

__device__ __forceinline__ void ldsm4t(uint32_t& r0, uint32_t& r1, uint32_t& r2, uint32_t& r3,
                                       uint32_t addr) {
    asm volatile("ldmatrix.sync.aligned.m8n8.x4.trans.shared.b16 {%0,%1,%2,%3}, [%4];"
                 : "=r"(r0), "=r"(r1), "=r"(r2), "=r"(r3) : "r"(addr));
}
__device__ __forceinline__ void mma16816(float* c, const uint32_t* a, uint32_t b0, uint32_t b1) {
    asm volatile(
        "mma.sync.aligned.m16n8k16.row.col.f32.bf16.bf16.f32 "
        "{%0,%1,%2,%3}, {%4,%5,%6,%7}, {%8,%9}, {%0,%1,%2,%3};"
        : "+f"(c[0]), "+f"(c[1]), "+f"(c[2]), "+f"(c[3])
        : "r"(a[0]), "r"(a[1]), "r"(a[2]), "r"(a[3]), "r"(b0), "r"(b1));
}
__device__ __forceinline__ uint32_t pack_bf16x2(float lo, float hi) {
    uint32_t r;
    asm("cvt.rn.bf16x2.f32 %0, %1, %2;" : "=r"(r) : "f"(hi), "f"(lo));
    return r;
}
__device__ __forceinline__ void split2(float vx, float vy, uint32_t& h, uint32_t& l) {
    h = pack_bf16x2(vx, vy);
    float hx = __bfloat162float(__ushort_as_bfloat16((unsigned short)(h & 0xffffu)));
    float hy = __bfloat162float(__ushort_as_bfloat16((unsigned short)(h >> 16)));
    l = pack_bf16x2(vx - hx, vy - hy);
}
__device__ __forceinline__ float warp_sum(float v) {
    #pragma unroll
    for (int off = 16; off; off >>= 1) v += __shfl_xor_sync(0xffffffffu, v, off);
    return v;
}
__device__ __forceinline__ float quad_sum(float v) {
    v += __shfl_xor_sync(0xffffffffu, v, 1);
    v += __shfl_xor_sync(0xffffffffu, v, 2);
    return v;
}

// ---------------- prep: split weights into 19-chunk SMEM-image ring ----------------
__global__ void prep_kernel(const float* __restrict__ W1, const float* __restrict__ W2)
{
    int idx = blockIdx.x * blockDim.x + threadIdx.x;
    const int TOT = NCHK * 16 * PITCH;   // 80256
    if (idx >= TOT) return;
    int c = idx / (16 * PITCH);
    int rem = idx - c * 16 * PITCH;
    int r = rem / PITCH, n = rem % PITCH;
    int k = c * 16 + r;
    float v = 0.f;
    if (n < 256) {
        if (c < 3) { if (k < 43) v = W1[k * 256 + n]; }
        else       v = W2[(k - 48) * 256 + n];
    }
    __nv_bfloat16 h = __float2bfloat16(v);
    __nv_bfloat16 l = __float2bfloat16(v - __bfloat162float(h));
    unsigned char* base = g_wimg + c * CHUNK_B + r * ROWB + n * 2;
    *(__nv_bfloat16*)base             = h;
    *(__nv_bfloat16*)(base + PLANE_B) = l;
}

// ---------------- main fused kernel ----------------
__global__ __launch_bounds__(THREADS, 2)
void fused_mma_kernel(const float* __restrict__ obs, const float* __restrict__ act,
                      const float* __restrict__ b1,  const float* __restrict__ g1,
                      const float* __restrict__ be1, const float* __restrict__ b2,
                      const float* __restrict__ g2,  const float* __restrict__ be2,
                      const float* __restrict__ W3,  const float* __restrict__ b3,
                      float* __restrict__ out)
{
    extern __shared__ char raw[];
    char* sm = (char*)((((uintptr_t)raw) + 127) & ~(uintptr_t)127);
    const uint32_t sbase = smem_u32(sm);
    const int tid = threadIdx.x, warp = tid >> 5, lane = tid & 31;
    const int mgrp = warp >> 2;             // 0..1 : rows mgrp*32..+31
    const int ngrp = warp & 3;              // 0..3 : cols ngrp*64..+63
    const int qr = lane >> 2;               // 0..7
    const int qc = (lane & 3) << 1;         // 0,2,4,6

    float* xsO  = (float*)(sm + A2H_OFF);           // [64][39] packed
    float* xsA  = (float*)(sm + A2H_OFF + 9984);    // [64][4]
    float* b1s  = (float*)(sm + VEC_OFF);
    float* g1s  = b1s + 256;  float* be1s = g1s + 256;
    float* b2s  = be1s + 256; float* g2s  = b2s + 256; float* be2s = g2s + 256;
    float* w3s  = be2s + 256;
    float* lnx  = (float*)(sm + LNX_OFF);           // [64 rows][4 ngrp][2]
    float* bsum = (float*)(sm + BSUM_OFF);
    unsigned int* flag = (unsigned int*)(sm + FLAG_OFF);

    const uint32_t mbf[2] = {sbase + MBAR_OFF,      sbase + MBAR_OFF + 8};
    const uint32_t mbe[2] = {sbase + MBAR_OFF + 16, sbase + MBAR_OFF + 24};
    const uint32_t xsb    =  sbase + MBAR_OFF + 32;
    const uint32_t xse    =  sbase + MBAR_OFF + 40;
    const uint32_t slot[2] = {sbase + WBUF_OFF, sbase + WBUF_OFF + CHUNK_B};

    b1s[tid] = b1[tid]; g1s[tid] = g1[tid]; be1s[tid] = be1[tid];
    b2s[tid] = b2[tid]; g2s[tid] = g2[tid]; be2s[tid] = be2[tid];
    w3s[tid] = W3[tid];

    if (tid == 0) {
        MBARRIER_INIT(mbf[0], 1); MBARRIER_INIT(mbf[1], 1);
        MBARRIER_INIT(mbe[0], 8); MBARRIER_INIT(mbe[1], 8);
        MBARRIER_INIT(xsb, 1);
        MBARRIER_INIT(xse, 8);
    }
    __syncthreads();

    const int ntl = (NTILES - blockIdx.x + GRID - 1) / GRID;
    const int total_ch = ntl * NCHK;

    if (tid == 0) {
        // prime xs for first tile
        MBARRIER_EXPECT_TX(xsb, 11008u);
        bulk_g2s(sbase + A2H_OFF, (const char*)obs + (size_t)blockIdx.x * 9984, 9984u, xsb);
        bulk_g2s(sbase + A2H_OFF + 9984, (const char*)act + (size_t)blockIdx.x * 1024, 1024u, xsb);
        // prime weight chunks 0,1
        MBARRIER_EXPECT_TX(mbf[0], CHUNK_B);
        bulk_g2s(slot[0], g_wimg, CHUNK_B, mbf[0]);
        if (total_ch > 1) {
            MBARRIER_EXPECT_TX(mbf[1], CHUNK_B);
            bulk_g2s(slot[1], g_wimg + CHUNK_B, CHUNK_B, mbf[1]);
        }
    }

    const uint32_t ldsm_off = (uint32_t)((lane & 15) * ROWB + ((lane >> 4) << 3) * 2 + ngrp * 128);
    int fp0 = 0, fp1 = 0, ep0 = 0, ep1 = 0, xp = 0, xp2 = 0;
    int g = 0;    // global chunk cursor
    int lt = 0;

    for (int tile = blockIdx.x; tile < NTILES; tile += GRID, ++lt) {
        MBARRIER_WAIT_PARITY(xsb, xp); xp ^= 1;

        float c[2][8][4];
        #pragma unroll
        for (int mf = 0; mf < 2; mf++)
            #pragma unroll
            for (int nf = 0; nf < 8; nf++)
                { c[mf][nf][0]=0.f; c[mf][nf][1]=0.f; c[mf][nf][2]=0.f; c[mf][nf][3]=0.f; }

        // ---- GEMM1: 3 weight chunks (k48), A from xs ----
        #pragma unroll 1
        for (int cc = 0; cc < 3; ++cc, ++g) {
            const int s = g & 1;
            MBARRIER_WAIT_PARITY(mbf[s], s ? fp1 : fp0);
            if (s) fp1 ^= 1; else fp0 ^= 1;

            uint32_t ah[2][4], al[2][4];
            #pragma unroll
            for (int mf = 0; mf < 2; mf++) {
                int r = mgrp * 32 + mf * 16 + qr;
                int c0 = cc * 16 + qc;
                float v[8];
                #pragma unroll
                for (int t = 0; t < 4; t++) {
                    int rr = r + (t & 1) * 8;
                    int cx = c0 + (t >> 1) * 8;
                    #pragma unroll
                    for (int e = 0; e < 2; e++) {
                        int ci = cx + e;
                        float vv = 0.f;
                        if (ci < SOBS) vv = xsO[rr * SOBS + ci];
                        else if (ci < SOBS + AACT) vv = xsA[rr * AACT + ci - SOBS];
                        v[t * 2 + e] = vv;
                    }
                }
                split2(v[0], v[1], ah[mf][0], al[mf][0]);
                split2(v[2], v[3], ah[mf][1], al[mf][1]);
                split2(v[4], v[5], ah[mf][2], al[mf][2]);
                split2(v[6], v[7], ah[mf][3], al[mf][3]);
            }

            uint32_t bb = slot[s] + ldsm_off;
            #pragma unroll
            for (int nf2 = 0; nf2 < 4; nf2++) {
                uint32_t h0, h1, h2, h3, l0, l1, l2, l3;
                ldsm4t(h0, h1, h2, h3, bb + nf2 * 32);
                ldsm4t(l0, l1, l2, l3, bb + PLANE_B + nf2 * 32);
                #pragma unroll
                for (int mf = 0; mf < 2; mf++) {
                    mma16816(c[mf][2*nf2],   ah[mf], h0, h1);
                    mma16816(c[mf][2*nf2+1], ah[mf], h2, h3);
                    mma16816(c[mf][2*nf2],   ah[mf], l0, l1);
                    mma16816(c[mf][2*nf2+1], ah[mf], l2, l3);
                    mma16816(c[mf][2*nf2],   al[mf], h0, h1);
                    mma16816(c[mf][2*nf2+1], al[mf], h2, h3);
                }
            }
            if (lane == 0) MBARRIER_ARRIVE(mbe[s]);
            if (tid == 0 && g + 2 < total_ch) {
                MBARRIER_WAIT_PARITY(mbe[s], s ? ep1 : ep0);
                if (s) ep1 ^= 1; else ep0 ^= 1;
                int cc2 = (g + 2) % NCHK;
                MBARRIER_EXPECT_TX(mbf[s], CHUNK_B);
                bulk_g2s(slot[s], g_wimg + cc2 * CHUNK_B, CHUNK_B, mbf[s]);
            }
        }

        // ---- LN1 (cross-4-warp stats) + ReLU -> A2 fragments ----
        {
            float st[4] = {0,0,0,0}, sq[4] = {0,0,0,0};
            #pragma unroll
            for (int mf = 0; mf < 2; mf++)
                #pragma unroll
                for (int nf = 0; nf < 8; nf++) {
                    float2 bb2 = *(const float2*)&b1s[ngrp * 64 + nf * 8 + qc];
                    float* cf = c[mf][nf];
                    cf[0] += bb2.x; cf[1] += bb2.y; cf[2] += bb2.x; cf[3] += bb2.y;
                    st[mf*2]   += cf[0] + cf[1];
                    sq[mf*2]    = fmaf(cf[0], cf[0], fmaf(cf[1], cf[1], sq[mf*2]));
                    st[mf*2+1] += cf[2] + cf[3];
                    sq[mf*2+1]  = fmaf(cf[2], cf[2], fmaf(cf[3], cf[3], sq[mf*2+1]));
                }
            #pragma unroll
            for (int i = 0; i < 4; i++) { st[i] = quad_sum(st[i]); sq[i] = quad_sum(sq[i]); }
            if ((lane & 3) == 0) {
                #pragma unroll
                for (int i = 0; i < 4; i++) {
                    int row = mgrp * 32 + (i >> 1) * 16 + (i & 1) * 8 + qr;
                    *(float2*)&lnx[(row * 4 + ngrp) * 2] = make_float2(st[i], sq[i]);
                }
            }
            __syncthreads();   // CTA-wide: also guards A2 writes vs other mgrp's xs reads
            float mu[4], rs[4];
            #pragma unroll
            for (int i = 0; i < 4; i++) {
                int row = mgrp * 32 + (i >> 1) * 16 + (i & 1) * 8 + qr;
                float4 p0 = *(const float4*)&lnx[row * 8];
                float4 p1 = *(const float4*)&lnx[row * 8 + 4];
                float s = p0.x + p0.z + p1.x + p1.z;
                float q = p0.y + p0.w + p1.y + p1.w;
                float m = s * (1.f / HID);
                float var = q * (1.f / HID) - m * m + EPS;
                float r0 = rsqrtf(var); r0 = r0 * (1.5f - 0.5f * var * r0 * r0);
                mu[i] = m; rs[i] = r0;
            }
            #pragma unroll
            for (int mf = 0; mf < 2; mf++) {
                float m0 = mu[mf*2], r0 = rs[mf*2], m1 = mu[mf*2+1], r1 = rs[mf*2+1];
                int midx = mgrp * 2 + mf;
                #pragma unroll
                for (int j = 0; j < 4; j++) {
                    uint32_t hh[4], ll[4];
                    #pragma unroll
                    for (int t = 0; t < 2; t++) {
                        int nf = 2 * j + t;
                        int ncol = ngrp * 64 + nf * 8 + qc;
                        float2 gg = *(const float2*)&g1s[ncol];
                        float2 ee = *(const float2*)&be1s[ncol];
                        float* cf = c[mf][nf];
                        float v0 = fmaxf((cf[0] - m0) * r0 * gg.x + ee.x, 0.f);
                        float v1 = fmaxf((cf[1] - m0) * r0 * gg.y + ee.y, 0.f);
                        float v2 = fmaxf((cf[2] - m1) * r1 * gg.x + ee.x, 0.f);
                        float v3 = fmaxf((cf[3] - m1) * r1 * gg.y + ee.y, 0.f);
                        split2(v0, v1, hh[t*2],   ll[t*2]);
                        split2(v2, v3, hh[t*2+1], ll[t*2+1]);
                    }
                    int ki = ngrp * 4 + j;
                    uint32_t so = (uint32_t)(((ki * 4 + midx) * 32 + lane) * 16);
                    *(uint4*)(sm + A2H_OFF + so) = make_uint4(hh[0], hh[1], hh[2], hh[3]);
                    *(uint4*)(sm + A2L_OFF + so) = make_uint4(ll[0], ll[1], ll[2], ll[3]);
                }
            }
            BAR_MGRP(1 + mgrp);   // A2 slots for this mgrp written; only same-mgrp warps read them
        }

        // ---- GEMM2: 16 weight chunks (k256), A from A2 fragments ----
        #pragma unroll
        for (int mf = 0; mf < 2; mf++)
            #pragma unroll
            for (int nf = 0; nf < 8; nf++)
                { c[mf][nf][0]=0.f; c[mf][nf][1]=0.f; c[mf][nf][2]=0.f; c[mf][nf][3]=0.f; }

        // -- sub-loop A: chunks ki 0..5 (these A2 slots alias the xs region) --
        #pragma unroll 1
        for (int cc = 3; cc < 9; ++cc, ++g) {
            const int s = g & 1;
            MBARRIER_WAIT_PARITY(mbf[s], s ? fp1 : fp0);
            if (s) fp1 ^= 1; else fp0 ^= 1;

            const int ki = cc - 3;
            uint32_t ah[2][4], al[2][4];
            #pragma unroll
            for (int mf = 0; mf < 2; mf++) {
                int midx = mgrp * 2 + mf;
                uint32_t so = (uint32_t)(((ki * 4 + midx) * 32 + lane) * 16);
                uint4 a4 = *(const uint4*)(sm + A2H_OFF + so);
                uint4 b4 = *(const uint4*)(sm + A2L_OFF + so);
                ah[mf][0]=a4.x; ah[mf][1]=a4.y; ah[mf][2]=a4.z; ah[mf][3]=a4.w;
                al[mf][0]=b4.x; al[mf][1]=b4.y; al[mf][2]=b4.z; al[mf][3]=b4.w;
            }

            uint32_t bb = slot[s] + ldsm_off;
            #pragma unroll
            for (int nf2 = 0; nf2 < 4; nf2++) {
                uint32_t h0, h1, h2, h3, l0, l1, l2, l3;
                ldsm4t(h0, h1, h2, h3, bb + nf2 * 32);
                ldsm4t(l0, l1, l2, l3, bb + PLANE_B + nf2 * 32);
                #pragma unroll
                for (int mf = 0; mf < 2; mf++) {
                    mma16816(c[mf][2*nf2],   ah[mf], h0, h1);
                    mma16816(c[mf][2*nf2+1], ah[mf], h2, h3);
                    mma16816(c[mf][2*nf2],   ah[mf], l0, l1);
                    mma16816(c[mf][2*nf2+1], ah[mf], l2, l3);
                    mma16816(c[mf][2*nf2],   al[mf], h0, h1);
                    mma16816(c[mf][2*nf2+1], al[mf], h2, h3);
                }
            }
            if (lane == 0) MBARRIER_ARRIVE(mbe[s]);
            if (tid == 0 && g + 2 < total_ch) {
                MBARRIER_WAIT_PARITY(mbe[s], s ? ep1 : ep0);
                if (s) ep1 ^= 1; else ep0 ^= 1;
                int cc2 = (g + 2) % NCHK;
                MBARRIER_EXPECT_TX(mbf[s], CHUNK_B);
                bulk_g2s(slot[s], g_wimg + cc2 * CHUNK_B, CHUNK_B, mbf[s]);
            }
        }

        // -- between sub-loops (once per tile, cold): release xs region, prefetch next xs --
        if (lane == 0) MBARRIER_ARRIVE(xse);
        if (tid == 0 && lt + 1 < ntl) {
            MBARRIER_WAIT_PARITY(xse, xp2);
            size_t nt = (size_t)(tile + GRID);
            MBARRIER_EXPECT_TX(xsb, 11008u);
            bulk_g2s(sbase + A2H_OFF, (const char*)obs + nt * 9984, 9984u, xsb);
            bulk_g2s(sbase + A2H_OFF + 9984, (const char*)act + nt * 1024, 1024u, xsb);
        }
        xp2 ^= 1;

        // -- sub-loop B: chunks ki 6..15 --
        #pragma unroll 1
        for (int cc = 9; cc < NCHK; ++cc, ++g) {
            const int s = g & 1;
            MBARRIER_WAIT_PARITY(mbf[s], s ? fp1 : fp0);
            if (s) fp1 ^= 1; else fp0 ^= 1;

            const int ki = cc - 3;
            uint32_t ah[2][4], al[2][4];
            #pragma unroll
            for (int mf = 0; mf < 2; mf++) {
                int midx = mgrp * 2 + mf;
                uint32_t so = (uint32_t)(((ki * 4 + midx) * 32 + lane) * 16);
                uint4 a4 = *(const uint4*)(sm + A2H_OFF + so);
                uint4 b4 = *(const uint4*)(sm + A2L_OFF + so);
                ah[mf][0]=a4.x; ah[mf][1]=a4.y; ah[mf][2]=a4.z; ah[mf][3]=a4.w;
                al[mf][0]=b4.x; al[mf][1]=b4.y; al[mf][2]=b4.z; al[mf][3]=b4.w;
            }

            uint32_t bb = slot[s] + ldsm_off;
            #pragma unroll
            for (int nf2 = 0; nf2 < 4; nf2++) {
                uint32_t h0, h1, h2, h3, l0, l1, l2, l3;
                ldsm4t(h0, h1, h2, h3, bb + nf2 * 32);
                ldsm4t(l0, l1, l2, l3, bb + PLANE_B + nf2 * 32);
                #pragma unroll
                for (int mf = 0; mf < 2; mf++) {
                    mma16816(c[mf][2*nf2],   ah[mf], h0, h1);
                    mma16816(c[mf][2*nf2+1], ah[mf], h2, h3);
                    mma16816(c[mf][2*nf2],   ah[mf], l0, l1);
                    mma16816(c[mf][2*nf2+1], ah[mf], l2, l3);
                    mma16816(c[mf][2*nf2],   al[mf], h0, h1);
                    mma16816(c[mf][2*nf2+1], al[mf], h2, h3);
                }
            }
            if (lane == 0) MBARRIER_ARRIVE(mbe[s]);
            if (tid == 0 && g + 2 < total_ch) {
                MBARRIER_WAIT_PARITY(mbe[s], s ? ep1 : ep0);
                if (s) ep1 ^= 1; else ep0 ^= 1;
                int cc2 = (g + 2) % NCHK;
                MBARRIER_EXPECT_TX(mbf[s], CHUNK_B);
                bulk_g2s(slot[s], g_wimg + cc2 * CHUNK_B, CHUNK_B, mbf[s]);
            }
        }

        // ---- LN2 + ReLU + dot(W3) ----
        float rp = 0.f;
        {
            float st[4] = {0,0,0,0}, sq[4] = {0,0,0,0};
            #pragma unroll
            for (int mf = 0; mf < 2; mf++)
                #pragma unroll
                for (int nf = 0; nf < 8; nf++) {
                    float2 bb2 = *(const float2*)&b2s[ngrp * 64 + nf * 8 + qc];
                    float* cf = c[mf][nf];
                    cf[0] += bb2.x; cf[1] += bb2.y; cf[2] += bb2.x; cf[3] += bb2.y;
                    st[mf*2]   += cf[0] + cf[1];
                    sq[mf*2]    = fmaf(cf[0], cf[0], fmaf(cf[1], cf[1], sq[mf*2]));
                    st[mf*2+1] += cf[2] + cf[3];
                    sq[mf*2+1]  = fmaf(cf[2], cf[2], fmaf(cf[3], cf[3], sq[mf*2+1]));
                }
            #pragma unroll
            for (int i = 0; i < 4; i++) { st[i] = quad_sum(st[i]); sq[i] = quad_sum(sq[i]); }
            if ((lane & 3) == 0) {
                #pragma unroll
                for (int i = 0; i < 4; i++) {
                    int row = mgrp * 32 + (i >> 1) * 16 + (i & 1) * 8 + qr;
                    *(float2*)&lnx[(row * 4 + ngrp) * 2] = make_float2(st[i], sq[i]);
                }
            }
            BAR_MGRP(1 + mgrp);   // lnx rows are mgrp-local
            float mu[4], rs[4];
            #pragma unroll
            for (int i = 0; i < 4; i++) {
                int row = mgrp * 32 + (i >> 1) * 16 + (i & 1) * 8 + qr;
                float4 p0 = *(const float4*)&lnx[row * 8];
                float4 p1 = *(const float4*)&lnx[row * 8 + 4];
                float s = p0.x + p0.z + p1.x + p1.z;
                float q = p0.y + p0.w + p1.y + p1.w;
                float m = s * (1.f / HID);
                float var = q * (1.f / HID) - m * m + EPS;
                float r0 = rsqrtf(var); r0 = r0 * (1.5f - 0.5f * var * r0 * r0);
                mu[i] = m; rs[i] = r0;
            }
            #pragma unroll
            for (int mf = 0; mf < 2; mf++) {
                float m0 = mu[mf*2], r0 = rs[mf*2], m1 = mu[mf*2+1], r1 = rs[mf*2+1];
                #pragma unroll
                for (int nf = 0; nf < 8; nf++) {
                    int ncol = ngrp * 64 + nf * 8 + qc;
                    float2 gg = *(const float2*)&g2s[ncol];
                    float2 ee = *(const float2*)&be2s[ncol];
                    float2 ww = *(const float2*)&w3s[ncol];
                    float* cf = c[mf][nf];
                    float v0 = fmaxf((cf[0] - m0) * r0 * gg.x + ee.x, 0.f);
                    float v1 = fmaxf((cf[1] - m0) * r0 * gg.y + ee.y, 0.f);
                    float v2 = fmaxf((cf[2] - m1) * r1 * gg.x + ee.x, 0.f);
                    float v3 = fmaxf((cf[3] - m1) * r1 * gg.y + ee.y, 0.f);
                    rp = fmaf(v0, ww.x, rp); rp = fmaf(v1, ww.y, rp);
                    rp = fmaf(v2, ww.x, rp); rp = fmaf(v3, ww.y, rp);
                }
            }
        }
        rp = warp_sum(rp);
        if (lane == 0) bsum[warp] = rp;
        __syncthreads();
        if (tid == 0) {
            float t = 0.f;
            #pragma unroll
            for (int w = 0; w < 8; w++) t += bsum[w];
            g_partials[tile] = t;
        }
        // (second tile-end sync dropped: bsum is next written only after the
        //  next tile's LN1 __syncthreads, which orders tid0's reads above)
    }

    // ---- last-block deterministic reduction into out[] ----
    __syncthreads();
    __threadfence();
    if (tid == 0) {
        unsigned int old = atomicAdd(&g_arrive, 1u);
        *flag = (old == GRID - 1) ? 1u : 0u;
    }
    __syncthreads();
    if (*flag) {
        __threadfence();
        float bb3 = b3[0];
        for (int b = tid; b < BATCH; b += THREADS) {
            float t = (float)TSEQ * bb3;
            #pragma unroll
            for (int i = 0; i < TPB; i++) t += __ldcg(&g_partials[b * TPB + i]);
            out[b] = t;
        }
        __syncthreads();
        if (tid == 0) { g_arrive = 0; __threadfence(); }
    }
}

extern "C" void kernel_launch(void* const* d_in, const int* in_sizes, int n_in,
                              void* d_out, int out_size)
{
    const float* obs = (const float*)d_in[0];
    const float* act = (const float*)d_in[1];
    const float* W1  = (const float*)d_in[2];
    const float* b1  = (const float*)d_in[3];
    const float* g1  = (const float*)d_in[4];
    const float* be1 = (const float*)d_in[5];
    const float* W2  = (const float*)d_in[6];
    const float* b2  = (const float*)d_in[7];
    const float* g2  = (const float*)d_in[8];
    const float* be2 = (const float*)d_in[9];
    const float* W3  = (const float*)d_in[10];
    const float* b3  = (const float*)d_in[11];

    prep_kernel<<<(NCHK * 16 * PITCH + 255) / 256, 256>>>(W1, W2);

    cudaFuncSetAttribute(fused_mma_kernel,
                         cudaFuncAttributeMaxDynamicSharedMemorySize, SMEM_DYN);
    fused_mma_kernel<<<GRID, THREADS, SMEM_DYN>>>(obs, act, b1, g1, be1, b2, g2, be2,
                                                  W3, b3, (float*)d_out);
}